// round 2
// baseline (speedup 1.0000x reference)
#include <cuda_runtime.h>

// Shapes (fixed by the problem):
//   input : 2 tensors float32 [2048, 8, 8, 64]  (re, im)      8,388,608 elems each
//   output: float32 [2, 2048, 8, 16, 64]                      33,554,432 elems
//
// Per block b (qubit q = 0 if b even else 5; m = 32 or 1):
//   top (d 0..7):  out[i] = S * in[i ^ m],                 S = 2^-0.25   (both re & im)
//   bot (d 8..15): out_re[i] = sgn * A * (re[i] - im[i])
//                  out_im[i] = sgn * A * (re[i] + im[i]),  A = 2^-0.75,
//                  sgn = (i & m) ? -1 : +1

#define S_CONST 0.8408964152537145f   // 2^-0.25
#define A_CONST 0.5946035575013605f   // 2^-0.75

__global__ void __launch_bounds__(256)
entangle_kernel(const float4* __restrict__ re4,
                const float4* __restrict__ im4,
                float4* __restrict__ out4,
                int n_f4)   // number of input float4's = 2,097,152
{
    int f = blockIdx.x * blockDim.x + threadIdx.x;
    if (f >= n_f4) return;

    // decode: f = (((b*8 + blk)*8 + d)*16 + i4)
    int i4   = f & 15;          // float4 index within the 64-wide row
    int rest = f >> 4;          // (b*8+blk)*8 + d
    int d    = rest & 7;
    int bblk = rest >> 3;       // b*8 + blk
    int blk  = bblk & 7;

    const bool even_blk = (blk & 1) == 0;   // qubit 0 (m=32) vs qubit 5 (m=1)

    float4 r = re4[f];
    float4 m = im4[f];

    // ---- top (X gate): gather at i^mask, scale by S ----
    float4 tr, ti;
    if (even_blk) {
        // m = 32 elements = 8 float4's: partner float4 at f^8 (same row)
        int fp = f ^ 8;
        float4 gr = re4[fp];
        float4 gi = im4[fp];
        tr = make_float4(S_CONST * gr.x, S_CONST * gr.y, S_CONST * gr.z, S_CONST * gr.w);
        ti = make_float4(S_CONST * gi.x, S_CONST * gi.y, S_CONST * gi.z, S_CONST * gi.w);
    } else {
        // m = 1: swap adjacent lanes within this float4
        tr = make_float4(S_CONST * r.y, S_CONST * r.x, S_CONST * r.w, S_CONST * r.z);
        ti = make_float4(S_CONST * m.y, S_CONST * m.x, S_CONST * m.w, S_CONST * m.z);
    }

    // ---- bot (Z gate): (re,im) -> sgn*A*(re-im, re+im) ----
    float4 br, bi;
    if (even_blk) {
        // sign uniform across the float4: depends on bit 5 of i0 = i4*4
        float sa = (i4 & 8) ? -A_CONST : A_CONST;
        br = make_float4(sa * (r.x - m.x), sa * (r.y - m.y),
                         sa * (r.z - m.z), sa * (r.w - m.w));
        bi = make_float4(sa * (r.x + m.x), sa * (r.y + m.y),
                         sa * (r.z + m.z), sa * (r.w + m.w));
    } else {
        // sign alternates per lane: +, -, +, -
        br = make_float4( A_CONST * (r.x - m.x), -A_CONST * (r.y - m.y),
                          A_CONST * (r.z - m.z), -A_CONST * (r.w - m.w));
        bi = make_float4( A_CONST * (r.x + m.x), -A_CONST * (r.y + m.y),
                          A_CONST * (r.z + m.z), -A_CONST * (r.w + m.w));
    }

    // ---- output addressing ----
    // out float4 layout: [2][2048][8][16][16f4]
    // top at d, bot at d+8; part stride = 2048*8*16*16 f4
    const int PS4 = 2048 * 8 * 16 * 16;           // 4,194,304
    int ot = (bblk * 16 + d) * 16 + i4;           // part 0 (real), top
    int ob = ot + 8 * 16;                         // bot: d+8

    out4[ot]        = tr;
    out4[ot + PS4]  = ti;
    out4[ob]        = br;
    out4[ob + PS4]  = bi;
}

extern "C" void kernel_launch(void* const* d_in, const int* in_sizes, int n_in,
                              void* d_out, int out_size)
{
    const float4* re4 = (const float4*)d_in[0];
    const float4* im4 = (const float4*)d_in[1];
    float4* out4      = (float4*)d_out;

    int n_f4 = in_sizes[0] / 4;   // 8,388,608 / 4 = 2,097,152
    int threads = 256;
    int blocks  = (n_f4 + threads - 1) / threads;   // 8192

    entangle_kernel<<<blocks, threads>>>(re4, im4, out4, n_f4);
}

// round 3
// speedup vs baseline: 1.0009x; 1.0009x over previous
#include <cuda_runtime.h>

// input : 2 tensors float32 [2048, 8, 8, 64]  (re, im)   8,388,608 elems each
// output: float32 [2, 2048, 8, 16, 64]                  33,554,432 elems
//
// Per block b (qubit q = 0 if b even else 5; mask m = 32 or 1):
//   top (d 0..7):  out[i] = S * in[i ^ m],              S = 2^-0.25
//   bot (d 8..15): out_re[i] = sgn * A * (re[i]-im[i])
//                  out_im[i] = sgn * A * (re[i]+im[i]), A = 2^-0.75,
//                  sgn = (i & m) ? -1 : +1
//
// Each thread owns the float4 PAIR {f, f^8} so every input float4 is loaded
// exactly once (the m=32 gather is resolved within the thread).

#define S_CONST 0.8408964152537145f   // 2^-0.25
#define A_CONST 0.5946035575013605f   // 2^-0.75

__device__ __forceinline__ float4 scale4(float4 v, float s) {
    return make_float4(s * v.x, s * v.y, s * v.z, s * v.w);
}
__device__ __forceinline__ float4 swap_scale4(float4 v, float s) {
    // lane swap for m=1: (x,y,z,w) -> (y,x,w,z), scaled
    return make_float4(s * v.y, s * v.x, s * v.w, s * v.z);
}

__global__ void __launch_bounds__(256)
entangle_pair_kernel(const float4* __restrict__ re4,
                     const float4* __restrict__ im4,
                     float4* __restrict__ out4,
                     int n_pairs)   // 1,048,576
{
    int t = blockIdx.x * blockDim.x + threadIdx.x;
    if (t >= n_pairs) return;

    // decode: t = ((bblk*8 + d)*8 + i8)
    int i8   = t & 7;           // low float4 index (0..7); partner at i8+8
    int rest = t >> 3;
    int d    = rest & 7;
    int bblk = rest >> 3;       // b*8 + blk
    int blk  = bblk & 7;
    const bool even_blk = (blk & 1) == 0;   // qubit 0 (m=32) vs qubit 5 (m=1)

    int f_lo = (bblk << 7) + (d << 4) + i8;
    int f_hi = f_lo + 8;

    // 4 independent loads up front (MLP)
    float4 r_lo = re4[f_lo];
    float4 r_hi = re4[f_hi];
    float4 m_lo = im4[f_lo];
    float4 m_hi = im4[f_hi];

    float4 tr_lo, tr_hi, ti_lo, ti_hi;   // top (X gate)
    float4 br_lo, br_hi, bi_lo, bi_hi;   // bot (Z gate)

    if (even_blk) {
        // m=32: top is the cross pair, scaled
        tr_lo = scale4(r_hi, S_CONST);  ti_lo = scale4(m_hi, S_CONST);
        tr_hi = scale4(r_lo, S_CONST);  ti_hi = scale4(m_lo, S_CONST);
        // bot sign: +A for lo half (bit5 clear), -A for hi half
        br_lo = make_float4( A_CONST * (r_lo.x - m_lo.x),  A_CONST * (r_lo.y - m_lo.y),
                             A_CONST * (r_lo.z - m_lo.z),  A_CONST * (r_lo.w - m_lo.w));
        bi_lo = make_float4( A_CONST * (r_lo.x + m_lo.x),  A_CONST * (r_lo.y + m_lo.y),
                             A_CONST * (r_lo.z + m_lo.z),  A_CONST * (r_lo.w + m_lo.w));
        br_hi = make_float4(-A_CONST * (r_hi.x - m_hi.x), -A_CONST * (r_hi.y - m_hi.y),
                            -A_CONST * (r_hi.z - m_hi.z), -A_CONST * (r_hi.w - m_hi.w));
        bi_hi = make_float4(-A_CONST * (r_hi.x + m_hi.x), -A_CONST * (r_hi.y + m_hi.y),
                            -A_CONST * (r_hi.z + m_hi.z), -A_CONST * (r_hi.w + m_hi.w));
    } else {
        // m=1: top swaps adjacent lanes within each float4
        tr_lo = swap_scale4(r_lo, S_CONST);  ti_lo = swap_scale4(m_lo, S_CONST);
        tr_hi = swap_scale4(r_hi, S_CONST);  ti_hi = swap_scale4(m_hi, S_CONST);
        // bot signs alternate per lane: +,-,+,-
        br_lo = make_float4( A_CONST * (r_lo.x - m_lo.x), -A_CONST * (r_lo.y - m_lo.y),
                             A_CONST * (r_lo.z - m_lo.z), -A_CONST * (r_lo.w - m_lo.w));
        bi_lo = make_float4( A_CONST * (r_lo.x + m_lo.x), -A_CONST * (r_lo.y + m_lo.y),
                             A_CONST * (r_lo.z + m_lo.z), -A_CONST * (r_lo.w + m_lo.w));
        br_hi = make_float4( A_CONST * (r_hi.x - m_hi.x), -A_CONST * (r_hi.y - m_hi.y),
                             A_CONST * (r_hi.z - m_hi.z), -A_CONST * (r_hi.w - m_hi.w));
        bi_hi = make_float4( A_CONST * (r_hi.x + m_hi.x), -A_CONST * (r_hi.y + m_hi.y),
                             A_CONST * (r_hi.z + m_hi.z), -A_CONST * (r_hi.w + m_hi.w));
    }

    // output float4 layout: [2][2048][8][16][16f4]; part stride (imag) = PS4
    const int PS4 = 2048 * 8 * 16 * 16;             // 4,194,304
    int ot_lo = (bblk * 16 + d) * 16 + i8;          // top, lo float4
    int ot_hi = ot_lo + 8;
    int ob_lo = ot_lo + 8 * 16;                     // bot: row d+8
    int ob_hi = ob_lo + 8;

    // streaming stores: output is write-once, keep it out of L2's way
    __stcs(&out4[ot_lo],       tr_lo);
    __stcs(&out4[ot_hi],       tr_hi);
    __stcs(&out4[ot_lo + PS4], ti_lo);
    __stcs(&out4[ot_hi + PS4], ti_hi);
    __stcs(&out4[ob_lo],       br_lo);
    __stcs(&out4[ob_hi],       br_hi);
    __stcs(&out4[ob_lo + PS4], bi_lo);
    __stcs(&out4[ob_hi + PS4], bi_hi);
}

extern "C" void kernel_launch(void* const* d_in, const int* in_sizes, int n_in,
                              void* d_out, int out_size)
{
    const float4* re4 = (const float4*)d_in[0];
    const float4* im4 = (const float4*)d_in[1];
    float4* out4      = (float4*)d_out;

    int n_pairs = in_sizes[0] / 8;   // 8,388,608 / 8 = 1,048,576
    int threads = 256;
    int blocks  = (n_pairs + threads - 1) / threads;   // 4096

    entangle_pair_kernel<<<blocks, threads>>>(re4, im4, out4, n_pairs);
}

// round 4
// speedup vs baseline: 1.0100x; 1.0091x over previous
#include <cuda_runtime.h>
#include <cstdint>

// input : 2 tensors float32 [2048, 8, 8, 64]  (re, im)   8,388,608 elems each
// output: float32 [2, 2048, 8, 16, 64]                  33,554,432 elems
//
// Per block b (qubit q = 0 if b even else 5; mask m = 32 or 1):
//   top (d 0..7):  out[i] = S * in[i ^ m],              S = 2^-0.25
//   bot (d 8..15): out_re[i] = sgn * A * (re[i]-im[i])
//                  out_im[i] = sgn * A * (re[i]+im[i]), A = 2^-0.75,
//                  sgn = (i & m) ? -1 : +1
//
// Each thread owns TWO adjacent float4s (8 floats) of the low half AND their
// m=32 partners (i^32), using 256-bit ld/st (sm_103a .v8.f32).

#define S_CONST 0.8408964152537145f   // 2^-0.25
#define A_CONST 0.5946035575013605f   // 2^-0.75

struct f8 { float v[8]; };

__device__ __forceinline__ f8 ldg256(const float* p) {
    f8 r;
    asm volatile("ld.global.nc.v8.f32 {%0,%1,%2,%3,%4,%5,%6,%7}, [%8];"
                 : "=f"(r.v[0]), "=f"(r.v[1]), "=f"(r.v[2]), "=f"(r.v[3]),
                   "=f"(r.v[4]), "=f"(r.v[5]), "=f"(r.v[6]), "=f"(r.v[7])
                 : "l"(p));
    return r;
}
__device__ __forceinline__ void stg256_cs(float* p, const f8& r) {
    asm volatile("st.global.cs.v8.f32 [%0], {%1,%2,%3,%4,%5,%6,%7,%8};"
                 :: "l"(p),
                    "f"(r.v[0]), "f"(r.v[1]), "f"(r.v[2]), "f"(r.v[3]),
                    "f"(r.v[4]), "f"(r.v[5]), "f"(r.v[6]), "f"(r.v[7])
                 : "memory");
}

__global__ void __launch_bounds__(256)
entangle_v8_kernel(const float* __restrict__ re,
                   const float* __restrict__ im,
                   float* __restrict__ out,
                   int n_threads)   // 524,288
{
    int t = blockIdx.x * blockDim.x + threadIdx.x;
    if (t >= n_threads) return;

    // decode: t = ((bblk*8 + d)*4 + j), j selects 8-float chunk of low half
    int j    = t & 3;           // chunk 0..3 -> elements j*8 .. j*8+7 of i<32
    int rest = t >> 2;
    int d    = rest & 7;
    int bblk = rest >> 3;       // b*8 + blk
    int blk  = bblk & 7;
    const bool even_blk = (blk & 1) == 0;   // qubit 0 (m=32) vs qubit 5 (m=1)

    // element offsets (floats)
    int e_lo = (bblk << 9) + (d << 6) + (j << 3);   // i in [0,32)
    int e_hi = e_lo + 32;                           // partner half (i^32)

    f8 r_lo = ldg256(re + e_lo);
    f8 r_hi = ldg256(re + e_hi);
    f8 m_lo = ldg256(im + e_lo);
    f8 m_hi = ldg256(im + e_hi);

    f8 tr_lo, tr_hi, ti_lo, ti_hi;   // top (X gate)
    f8 br_lo, br_hi, bi_lo, bi_hi;   // bot (Z gate)

    if (even_blk) {
        // m=32: top is the cross half, scaled; bot sign = +A (lo) / -A (hi)
        #pragma unroll
        for (int k = 0; k < 8; k++) {
            tr_lo.v[k] = S_CONST * r_hi.v[k];
            ti_lo.v[k] = S_CONST * m_hi.v[k];
            tr_hi.v[k] = S_CONST * r_lo.v[k];
            ti_hi.v[k] = S_CONST * m_lo.v[k];
            br_lo.v[k] =  A_CONST * (r_lo.v[k] - m_lo.v[k]);
            bi_lo.v[k] =  A_CONST * (r_lo.v[k] + m_lo.v[k]);
            br_hi.v[k] = -A_CONST * (r_hi.v[k] - m_hi.v[k]);
            bi_hi.v[k] = -A_CONST * (r_hi.v[k] + m_hi.v[k]);
        }
    } else {
        // m=1: top swaps adjacent lanes; bot sign alternates per lane +,-
        #pragma unroll
        for (int k = 0; k < 8; k++) {
            int ks = k ^ 1;
            float sgn = (k & 1) ? -A_CONST : A_CONST;
            tr_lo.v[k] = S_CONST * r_lo.v[ks];
            ti_lo.v[k] = S_CONST * m_lo.v[ks];
            tr_hi.v[k] = S_CONST * r_hi.v[ks];
            ti_hi.v[k] = S_CONST * m_hi.v[ks];
            br_lo.v[k] = sgn * (r_lo.v[k] - m_lo.v[k]);
            bi_lo.v[k] = sgn * (r_lo.v[k] + m_lo.v[k]);
            br_hi.v[k] = sgn * (r_hi.v[k] - m_hi.v[k]);
            bi_hi.v[k] = sgn * (r_hi.v[k] + m_hi.v[k]);
        }
    }

    // output element layout: [2][2048][8][16][64]; imag part stride PS
    const int PS = 2048 * 8 * 16 * 64;              // 16,777,216
    int ot_lo = (bblk * 16 + d) * 64 + (j << 3);    // top row d, elems [j*8..)
    int ot_hi = ot_lo + 32;
    int ob_lo = ot_lo + 8 * 64;                     // bot row d+8
    int ob_hi = ob_lo + 32;

    stg256_cs(out + ot_lo,      tr_lo);
    stg256_cs(out + ot_hi,      tr_hi);
    stg256_cs(out + ot_lo + PS, ti_lo);
    stg256_cs(out + ot_hi + PS, ti_hi);
    stg256_cs(out + ob_lo,      br_lo);
    stg256_cs(out + ob_hi,      br_hi);
    stg256_cs(out + ob_lo + PS, bi_lo);
    stg256_cs(out + ob_hi + PS, bi_hi);
}

extern "C" void kernel_launch(void* const* d_in, const int* in_sizes, int n_in,
                              void* d_out, int out_size)
{
    const float* re = (const float*)d_in[0];
    const float* im = (const float*)d_in[1];
    float* out      = (float*)d_out;

    int n_threads = in_sizes[0] / 16;   // 8,388,608 / 16 = 524,288
    int threads = 256;
    int blocks  = (n_threads + threads - 1) / threads;   // 2048

    entangle_v8_kernel<<<blocks, threads>>>(re, im, out, n_threads);
}